// round 4
// baseline (speedup 1.0000x reference)
#include <cuda_runtime.h>
#include <math.h>

#define BB 32
#define SS 512
#define DD 768
#define KK 3
#define TWOD 1536

// ---------------- device scratch (no allocs allowed) ----------------
__device__ __align__(16) float g_WeffT[KK][TWOD];   // W_eff transposed: [k][d]
__device__ float g_beff[KK];
__device__ __align__(16) float g_logits[BB * SS * KK];

// ---------------- kernel A: W_eff = W_cnn @ W_dense, b_eff ----------------
__global__ void __launch_bounds__(128) weff_kernel(const float* __restrict__ Wc,
                                                   const float* __restrict__ Wd,
                                                   const float* __restrict__ bc,
                                                   const float* __restrict__ bd) {
    // let the dependent logits kernel launch & start its prologue immediately
    cudaTriggerProgrammaticLaunchCompletion();

    __shared__ float4 sWd[576];                 // 2304 floats = 9 KB
    int tid = threadIdx.x;
    for (int i = tid; i < 576; i += 128) sWd[i] = __ldg(((const float4*)Wd) + i);

    int gw = blockIdx.x * 4 + (tid >> 5);
    int lane = tid & 31;

    float4 x[6];
    if (gw <= TWOD) {
        const float4* s4 = (const float4*)((gw < TWOD) ? (Wc + (size_t)gw * DD) : bc);
        #pragma unroll
        for (int it = 0; it < 6; it++) x[it] = __ldg(s4 + it * 32 + lane);
    }
    __syncthreads();
    if (gw > TWOD) return;

    float a0 = 0.f, a1 = 0.f, a2 = 0.f;
    #pragma unroll
    for (int it = 0; it < 6; it++) {
        int i = it * 32 + lane;
        float4 wA = sWd[i * 3 + 0];
        float4 wB = sWd[i * 3 + 1];
        float4 wC = sWd[i * 3 + 2];
        float4 v = x[it];
        a0 = fmaf(v.x, wA.x, a0); a1 = fmaf(v.x, wA.y, a1); a2 = fmaf(v.x, wA.z, a2);
        a0 = fmaf(v.y, wA.w, a0); a1 = fmaf(v.y, wB.x, a1); a2 = fmaf(v.y, wB.y, a2);
        a0 = fmaf(v.z, wB.z, a0); a1 = fmaf(v.z, wB.w, a1); a2 = fmaf(v.z, wC.x, a2);
        a0 = fmaf(v.w, wC.y, a0); a1 = fmaf(v.w, wC.z, a1); a2 = fmaf(v.w, wC.w, a2);
    }
    #pragma unroll
    for (int o = 16; o; o >>= 1) {
        a0 += __shfl_xor_sync(0xffffffffu, a0, o);
        a1 += __shfl_xor_sync(0xffffffffu, a1, o);
        a2 += __shfl_xor_sync(0xffffffffu, a2, o);
    }
    if (lane == 0) {
        if (gw < TWOD) {
            g_WeffT[0][gw] = a0;
            g_WeffT[1][gw] = a1;
            g_WeffT[2][gw] = a2;
        } else {
            g_beff[0] = a0 + bd[0];
            g_beff[1] = a1 + bd[1];
            g_beff[2] = a2 + bd[2];
        }
    }
}

// ---------------- kernel B: logits ----------------
// one warp per 4 (b,s) rows. PDL: prefetch x before grid-dep-sync, W_eff after.
__global__ void __launch_bounds__(128) logits_kernel(const float* __restrict__ hidden,
                                                     const float* __restrict__ wsub) {
    // let crf launch & run its input-only prologue under us
    cudaTriggerProgrammaticLaunchCompletion();

    int gw = blockIdx.x * 4 + (threadIdx.x >> 5);   // 0..4095
    int lane = threadIdx.x & 31;
    bool active = (gw < (BB * SS) / 4);
    int r0 = gw * 4;

    const float4* hp[4];
    const float4* sp[4];
    if (active) {
        #pragma unroll
        for (int r = 0; r < 4; r++) {
            hp[r] = (const float4*)(hidden + (size_t)(r0 + r) * DD);
            sp[r] = (const float4*)(wsub + (size_t)(r0 + r) * DD);
        }
    }

    // prefetch hidden-half iterations 0..2 for all 4 rows (independent of weff)
    float4 pre[3][4];
    if (active) {
        #pragma unroll
        for (int it = 0; it < 3; it++) {
            int i = it * 32 + lane;
            #pragma unroll
            for (int r = 0; r < 4; r++) pre[it][r] = __ldg(hp[r] + i);
        }
    }

    // wait for weff's output to be visible
    cudaGridDependencySynchronize();
    if (!active) return;

    const float4* e0 = (const float4*)g_WeffT[0];
    const float4* e1 = (const float4*)g_WeffT[1];
    const float4* e2 = (const float4*)g_WeffT[2];

    float acc[4][3];
    #pragma unroll
    for (int r = 0; r < 4; r++) { acc[r][0] = 0.f; acc[r][1] = 0.f; acc[r][2] = 0.f; }

    #pragma unroll
    for (int it = 0; it < 6; it++) {
        int i = it * 32 + lane;
        float4 xx[4];
        if (it < 3) {
            #pragma unroll
            for (int r = 0; r < 4; r++) xx[r] = pre[it][r];
        } else {
            #pragma unroll
            for (int r = 0; r < 4; r++) xx[r] = __ldg(hp[r] + i);
        }
        float4 w0 = __ldg(e0 + i), w1 = __ldg(e1 + i), w2 = __ldg(e2 + i);
        #pragma unroll
        for (int r = 0; r < 4; r++) {
            float4 x = xx[r];
            acc[r][0] = fmaf(x.x, w0.x, fmaf(x.y, w0.y, fmaf(x.z, w0.z, fmaf(x.w, w0.w, acc[r][0]))));
            acc[r][1] = fmaf(x.x, w1.x, fmaf(x.y, w1.y, fmaf(x.z, w1.z, fmaf(x.w, w1.w, acc[r][1]))));
            acc[r][2] = fmaf(x.x, w2.x, fmaf(x.y, w2.y, fmaf(x.z, w2.z, fmaf(x.w, w2.w, acc[r][2]))));
        }
    }
    #pragma unroll
    for (int it = 0; it < 6; it++) {
        int i = it * 32 + lane;
        int j = i + DD / 4;
        float4 xx[4];
        #pragma unroll
        for (int r = 0; r < 4; r++) xx[r] = __ldg(sp[r] + i);
        float4 w0 = __ldg(e0 + j), w1 = __ldg(e1 + j), w2 = __ldg(e2 + j);
        #pragma unroll
        for (int r = 0; r < 4; r++) {
            float4 x = xx[r];
            acc[r][0] = fmaf(x.x, w0.x, fmaf(x.y, w0.y, fmaf(x.z, w0.z, fmaf(x.w, w0.w, acc[r][0]))));
            acc[r][1] = fmaf(x.x, w1.x, fmaf(x.y, w1.y, fmaf(x.z, w1.z, fmaf(x.w, w1.w, acc[r][1]))));
            acc[r][2] = fmaf(x.x, w2.x, fmaf(x.y, w2.y, fmaf(x.z, w2.z, fmaf(x.w, w2.w, acc[r][2]))));
        }
    }
    #pragma unroll
    for (int r = 0; r < 4; r++) {
        #pragma unroll
        for (int k = 0; k < 3; k++) {
            float v = acc[r][k];
            #pragma unroll
            for (int o = 16; o; o >>= 1) v += __shfl_xor_sync(0xffffffffu, v, o);
            acc[r][k] = v;
        }
    }
    if (lane == 0) {
        #pragma unroll
        for (int r = 0; r < 4; r++) {
            float* o = g_logits + (size_t)(r0 + r) * KK;
            o[0] = acc[r][0] + g_beff[0];
            o[1] = acc[r][1] + g_beff[1];
            o[2] = acc[r][2] + g_beff[2];
        }
    }
}

// ---------------- CRF helpers ----------------
#define SENT (-1e38f)

__device__ __forceinline__ float lse3(float x, float y, float z) {
    float m = fmaxf(fmaxf(x, y), z);
    if (m < -1e30f) return SENT;
    return m + __logf(__expf(x - m) + __expf(y - m) + __expf(z - m));
}

__device__ __forceinline__ int mapcompose(int f, int g) {
    int h0 = (f >> (2 * (g & 3))) & 3;
    int h1 = (f >> (2 * ((g >> 2) & 3))) & 3;
    int h2 = (f >> (2 * ((g >> 4) & 3))) & 3;
    return h0 | (h1 << 2) | (h2 << 4);
}
#define IDMAP 0x24

// ---------------- kernel C: CRF ----------------
__global__ void __launch_bounds__(128) crf_kernel(const float* __restrict__ trans,
                                                  const int* __restrict__ tgt,
                                                  float* __restrict__ out,
                                                  int out_size) {
    __shared__ float sh_log[SS * KK];
    __shared__ int sh_tgt[SS];
    __shared__ int sh_bp[SS];
    __shared__ int sh_seqlen;
    __shared__ int sh_init_tag;
    __shared__ float sh_lognorm, sh_unary, sh_binary;

    int b = blockIdx.x;
    int tid = threadIdx.x;
    int lane = tid & 31;
    int wid = tid >> 5;
    if (tid == 0) sh_seqlen = 0;

    // ---- prologue: inputs only (runs under logits via PDL) ----
    for (int i = tid; i < SS; i += 128) sh_tgt[i] = tgt[b * SS + i];
    __syncthreads();
    {
        int cnt = 0;
        for (int i = tid; i < SS; i += 128) cnt += (sh_tgt[i] >= 1);
        #pragma unroll
        for (int o = 16; o; o >>= 1) cnt += __shfl_xor_sync(0xffffffffu, cnt, o);
        if (lane == 0) atomicAdd(&sh_seqlen, cnt);
    }

    // wait for logits
    cudaGridDependencySynchronize();

    const float* lg = g_logits + (size_t)b * SS * KK;
    for (int i = tid; i < SS * KK; i += 128) sh_log[i] = lg[i];
    __syncthreads();
    int L = sh_seqlen;

    if (wid == 0) {
        // ---- forward LSE via (lse,+) semiring matrix scan ----
        int idx = L - 1;
        if (idx < 0) idx = 0;
        if (idx > SS - 1) idx = SS - 1;
        float t00 = trans[0], t01 = trans[1], t02 = trans[2];
        float t10 = trans[3], t11 = trans[4], t12 = trans[5];
        float t20 = trans[6], t21 = trans[7], t22 = trans[8];

        float p00 = 0.f,  p01 = SENT, p02 = SENT;
        float p10 = SENT, p11 = 0.f,  p12 = SENT;
        float p20 = SENT, p21 = SENT, p22 = 0.f;

        int tstart = 1 + lane * 16;
        for (int s = 0; s < 16; s++) {
            int t = tstart + s;
            if (t > idx) break;
            float l0 = sh_log[t * 3 + 0], l1 = sh_log[t * 3 + 1], l2 = sh_log[t * 3 + 2];
            float q00 = lse3(p00 + t00, p01 + t10, p02 + t20) + l0;
            float q01 = lse3(p00 + t01, p01 + t11, p02 + t21) + l1;
            float q02 = lse3(p00 + t02, p01 + t12, p02 + t22) + l2;
            float q10 = lse3(p10 + t00, p11 + t10, p12 + t20) + l0;
            float q11 = lse3(p10 + t01, p11 + t11, p12 + t21) + l1;
            float q12 = lse3(p10 + t02, p11 + t12, p12 + t22) + l2;
            float q20 = lse3(p20 + t00, p21 + t10, p22 + t20) + l0;
            float q21 = lse3(p20 + t01, p21 + t11, p22 + t21) + l1;
            float q22 = lse3(p20 + t02, p21 + t12, p22 + t22) + l2;
            p00 = q00; p01 = q01; p02 = q02;
            p10 = q10; p11 = q11; p12 = q12;
            p20 = q20; p21 = q21; p22 = q22;
        }
        for (int d = 1; d < 32; d <<= 1) {
            float q00 = __shfl_down_sync(0xffffffffu, p00, d);
            float q01 = __shfl_down_sync(0xffffffffu, p01, d);
            float q02 = __shfl_down_sync(0xffffffffu, p02, d);
            float q10 = __shfl_down_sync(0xffffffffu, p10, d);
            float q11 = __shfl_down_sync(0xffffffffu, p11, d);
            float q12 = __shfl_down_sync(0xffffffffu, p12, d);
            float q20 = __shfl_down_sync(0xffffffffu, p20, d);
            float q21 = __shfl_down_sync(0xffffffffu, p21, d);
            float q22 = __shfl_down_sync(0xffffffffu, p22, d);
            if ((lane & (2 * d - 1)) == 0) {
                float r00 = lse3(p00 + q00, p01 + q10, p02 + q20);
                float r01 = lse3(p00 + q01, p01 + q11, p02 + q21);
                float r02 = lse3(p00 + q02, p01 + q12, p02 + q22);
                float r10 = lse3(p10 + q00, p11 + q10, p12 + q20);
                float r11 = lse3(p10 + q01, p11 + q11, p12 + q21);
                float r12 = lse3(p10 + q02, p11 + q12, p12 + q22);
                float r20 = lse3(p20 + q00, p21 + q10, p22 + q20);
                float r21 = lse3(p20 + q01, p21 + q11, p22 + q21);
                float r22 = lse3(p20 + q02, p21 + q12, p22 + q22);
                p00 = r00; p01 = r01; p02 = r02;
                p10 = r10; p11 = r11; p12 = r12;
                p20 = r20; p21 = r21; p22 = r22;
            }
        }
        if (lane == 0) {
            float a0 = sh_log[0], a1 = sh_log[1], a2 = sh_log[2];
            float f0 = lse3(a0 + p00, a1 + p10, a2 + p20);
            float f1 = lse3(a0 + p01, a1 + p11, a2 + p21);
            float f2 = lse3(a0 + p02, a1 + p12, a2 + p22);
            float ln = lse3(f0, f1, f2);
            sh_lognorm = (L <= 0) ? 0.0f : ln;
        }
    } else if (wid == 1) {
        // ---- sequential viterbi forward (bit-exact order) with logits prefetch ----
        if (lane == 0) {
            float t00 = trans[0], t01 = trans[1], t02 = trans[2];
            float t10 = trans[3], t11 = trans[4], t12 = trans[5];
            float t20 = trans[6], t21 = trans[7], t22 = trans[8];
            float a0 = sh_log[0], a1 = sh_log[1], a2 = sh_log[2];
            float l0n = sh_log[3], l1n = sh_log[4], l2n = sh_log[5];
            for (int t = 1; t < L; t++) {
                float l0 = l0n, l1 = l1n, l2 = l2n;
                int tn = (t + 1 < SS - 1) ? (t + 1) : (SS - 1);
                l0n = sh_log[tn * 3 + 0]; l1n = sh_log[tn * 3 + 1]; l2n = sh_log[tn * 3 + 2];
                float x0 = a0 + t00, x1 = a1 + t10, x2 = a2 + t20;
                float bst0 = x0; int bi0 = 0;
                if (x1 > bst0) { bst0 = x1; bi0 = 1; }
                if (x2 > bst0) { bst0 = x2; bi0 = 2; }
                float y0 = a0 + t01, y1 = a1 + t11, y2 = a2 + t21;
                float bst1 = y0; int bi1 = 0;
                if (y1 > bst1) { bst1 = y1; bi1 = 1; }
                if (y2 > bst1) { bst1 = y2; bi1 = 2; }
                float z0 = a0 + t02, z1 = a1 + t12, z2 = a2 + t22;
                float bst2 = z0; int bi2 = 0;
                if (z1 > bst2) { bst2 = z1; bi2 = 1; }
                if (z2 > bst2) { bst2 = z2; bi2 = 2; }
                sh_bp[t] = bi0 | (bi1 << 2) | (bi2 << 4);
                a0 = l0 + bst0; a1 = l1 + bst1; a2 = l2 + bst2;
            }
            int tag = 0;
            float bst = a0;
            if (a1 > bst) { bst = a1; tag = 1; }
            if (a2 > bst) { bst = a2; tag = 2; }
            sh_init_tag = (L > 0) ? tag : 0;
        }
        __syncwarp();
        // ---- parallel traceback: suffix scan over packed tag-maps ----
        int init_tag = sh_init_tag;
        bool has_tags = (out_size >= BB * SS);
        int maps[16];
        int acc = IDMAP;
        #pragma unroll
        for (int s = 0; s < 16; s++) {
            int u = lane * 16 + s;
            int t = 510 - u;
            int m = IDMAP;
            if (u <= 510 && t <= L - 2) m = sh_bp[t + 1];
            maps[s] = m;
            acc = mapcompose(m, acc);
        }
        #pragma unroll
        for (int d = 1; d < 32; d <<= 1) {
            int peer = __shfl_up_sync(0xffffffffu, acc, d);
            if (lane >= d) acc = mapcompose(acc, peer);
        }
        int excl = __shfl_up_sync(0xffffffffu, acc, 1);
        if (lane == 0) excl = IDMAP;
        if (has_tags) {
            int g = excl;
            #pragma unroll
            for (int s = 0; s < 16; s++) {
                int u = lane * 16 + s;
                g = mapcompose(maps[s], g);
                if (u <= 510) {
                    int t = 510 - u;
                    int tagt = (t <= L - 1) ? ((g >> (2 * init_tag)) & 3) : 0;
                    out[b * SS + t] = (float)tagt;
                }
            }
            if (lane == 0) {
                int t511 = (L - 1 == SS - 1) ? init_tag : 0;
                out[b * SS + (SS - 1)] = (float)t511;
            }
        }
    } else if (wid == 2) {
        float u = 0.f;
        for (int s = lane; s < SS; s += 32)
            if (s < L) u += sh_log[s * 3 + sh_tgt[s]];
        #pragma unroll
        for (int o = 16; o; o >>= 1) u += __shfl_xor_sync(0xffffffffu, u, o);
        if (lane == 0) sh_unary = u;
    } else {
        float v = 0.f;
        for (int s = lane; s < SS - 1; s += 32)
            if (s < L - 1) v += trans[sh_tgt[s] * 3 + sh_tgt[s + 1]];
        #pragma unroll
        for (int o = 16; o; o >>= 1) v += __shfl_xor_sync(0xffffffffu, v, o);
        if (lane == 0) sh_binary = v;
    }
    __syncthreads();

    bool has_tags = (out_size >= BB * SS);
    int ll_off = has_tags ? (BB * SS) : 0;
    if (out_size >= ll_off + BB && tid == 0) {
        out[ll_off + b] = sh_unary + sh_binary - sh_lognorm;
    }
}

// ---------------- launch ----------------
extern "C" void kernel_launch(void* const* d_in, const int* in_sizes, int n_in,
                              void* d_out, int out_size) {
    const float *hidden = nullptr, *wsub = nullptr, *Wc = nullptr, *bc = nullptr;
    const float *Wd = nullptr, *bd = nullptr, *trans = nullptr;
    const int* tgt = nullptr;

    for (int i = 0; i < n_in; i++) {
        int sz = in_sizes[i];
        if (sz == BB * SS * DD) {
            if (!hidden) hidden = (const float*)d_in[i];
            else wsub = (const float*)d_in[i];
        } else if (sz == BB * SS) {
            tgt = (const int*)d_in[i];
        } else if (sz == TWOD * DD) {
            Wc = (const float*)d_in[i];
        } else if (sz == DD) {
            bc = (const float*)d_in[i];
        } else if (sz == DD * KK) {
            Wd = (const float*)d_in[i];
        } else if (sz == KK) {
            bd = (const float*)d_in[i];
        } else if (sz == KK * KK) {
            trans = (const float*)d_in[i];
        }
    }

    // A: weff (normal launch, triggers early PDL completion for B)
    weff_kernel<<<(TWOD + 4) / 4, 128>>>(Wc, Wd, bc, bd);

    // B: logits with programmatic dependent launch on A
    {
        cudaLaunchConfig_t cfg = {};
        cfg.gridDim = dim3((BB * SS) / 16, 1, 1);
        cfg.blockDim = dim3(128, 1, 1);
        cudaLaunchAttribute attr[1];
        attr[0].id = cudaLaunchAttributeProgrammaticStreamSerialization;
        attr[0].val.programmaticStreamSerializationAllowed = 1;
        cfg.attrs = attr;
        cfg.numAttrs = 1;
        cudaLaunchKernelEx(&cfg, logits_kernel, hidden, wsub);
    }

    // C: crf with programmatic dependent launch on B
    {
        cudaLaunchConfig_t cfg = {};
        cfg.gridDim = dim3(BB, 1, 1);
        cfg.blockDim = dim3(128, 1, 1);
        cudaLaunchAttribute attr[1];
        attr[0].id = cudaLaunchAttributeProgrammaticStreamSerialization;
        attr[0].val.programmaticStreamSerializationAllowed = 1;
        cfg.attrs = attr;
        cfg.numAttrs = 1;
        cudaLaunchKernelEx(&cfg, crf_kernel, trans, tgt, (float*)d_out, out_size);
    }
}

// round 5
// speedup vs baseline: 1.7181x; 1.7181x over previous
#include <cuda_runtime.h>
#include <math.h>

#define BB 32
#define SS 512
#define DD 768
#define KK 3
#define TWOD 1536

#define NB 512          // blocks (4 per SM guaranteed resident)
#define NT 256          // threads per block (8 warps)
#define NWARPS (NB * 8) // 4096 global warps

// ---------------- device scratch (no allocs allowed) ----------------
__device__ __align__(16) float g_WeffT[KK][TWOD];
__device__ float g_beff[KK];
__device__ __align__(16) float g_logits[BB * SS * KK];
__device__ unsigned long long g_bar[2];   // generation counters (never reset)

// ---------------- grid barrier (all blocks resident) ----------------
__device__ __forceinline__ void grid_barrier(int which) {
    __syncthreads();
    if (threadIdx.x == 0) {
        __threadfence();                                    // release my writes
        unsigned long long my =
            atomicAdd(&g_bar[which], 1ULL) + 1ULL;          // my arrival number
        unsigned long long gen = (my + NB - 1) / NB;        // generation I belong to
        unsigned long long target = gen * (unsigned long long)NB;
        volatile unsigned long long* p = (volatile unsigned long long*)&g_bar[which];
        while (*p < target) { __nanosleep(128); }
        __threadfence();                                    // acquire others' writes
    }
    __syncthreads();
}

// ---------------- CRF helpers ----------------
#define SENT (-1e38f)

__device__ __forceinline__ float lse3(float x, float y, float z) {
    float m = fmaxf(fmaxf(x, y), z);
    if (m < -1e30f) return SENT;
    return m + __logf(__expf(x - m) + __expf(y - m) + __expf(z - m));
}

__device__ __forceinline__ int mapcompose(int f, int g) {
    int h0 = (f >> (2 * (g & 3))) & 3;
    int h1 = (f >> (2 * ((g >> 2) & 3))) & 3;
    int h2 = (f >> (2 * ((g >> 4) & 3))) & 3;
    return h0 | (h1 << 2) | (h2 << 4);
}
#define IDMAP 0x24

// ---------------- the one kernel ----------------
__global__ void __launch_bounds__(NT, 4)
fused_kernel(const float* __restrict__ hidden, const float* __restrict__ wsub,
             const float* __restrict__ Wc,     const float* __restrict__ Wd,
             const float* __restrict__ bc,     const float* __restrict__ bd,
             const float* __restrict__ trans,  const int* __restrict__ tgt,
             float* __restrict__ out,          int out_size) {
    __shared__ float sh_log[SS * KK];
    __shared__ int sh_tgt[SS];
    __shared__ int sh_bp[SS];
    __shared__ int sh_seqlen;
    __shared__ int sh_init_tag;
    __shared__ float sh_lognorm, sh_unary, sh_binary;

    int tid = threadIdx.x;
    int lane = tid & 31;
    int wid = tid >> 5;                       // 0..7
    int gw = blockIdx.x * 8 + wid;            // 0..4095

    // ================= PHASE 1: W_eff = W_cnn @ W_dense =================
    if (gw <= TWOD) {
        const float4* s4 = (const float4*)((gw < TWOD) ? (Wc + (size_t)gw * DD) : bc);
        const float4* wd4 = (const float4*)Wd;
        float a0 = 0.f, a1 = 0.f, a2 = 0.f;
        float4 x[6];
        #pragma unroll
        for (int it = 0; it < 6; it++) x[it] = __ldg(s4 + it * 32 + lane);
        #pragma unroll
        for (int it = 0; it < 6; it++) {
            int i = it * 32 + lane;
            float4 wA = __ldg(wd4 + i * 3 + 0);
            float4 wB = __ldg(wd4 + i * 3 + 1);
            float4 wC = __ldg(wd4 + i * 3 + 2);
            float4 v = x[it];
            a0 = fmaf(v.x, wA.x, a0); a1 = fmaf(v.x, wA.y, a1); a2 = fmaf(v.x, wA.z, a2);
            a0 = fmaf(v.y, wA.w, a0); a1 = fmaf(v.y, wB.x, a1); a2 = fmaf(v.y, wB.y, a2);
            a0 = fmaf(v.z, wB.z, a0); a1 = fmaf(v.z, wB.w, a1); a2 = fmaf(v.z, wC.x, a2);
            a0 = fmaf(v.w, wC.y, a0); a1 = fmaf(v.w, wC.z, a1); a2 = fmaf(v.w, wC.w, a2);
        }
        #pragma unroll
        for (int o = 16; o; o >>= 1) {
            a0 += __shfl_xor_sync(0xffffffffu, a0, o);
            a1 += __shfl_xor_sync(0xffffffffu, a1, o);
            a2 += __shfl_xor_sync(0xffffffffu, a2, o);
        }
        if (lane == 0) {
            if (gw < TWOD) {
                g_WeffT[0][gw] = a0;
                g_WeffT[1][gw] = a1;
                g_WeffT[2][gw] = a2;
            } else {
                g_beff[0] = a0 + bd[0];
                g_beff[1] = a1 + bd[1];
                g_beff[2] = a2 + bd[2];
            }
        }
    }

    grid_barrier(0);

    // ================= PHASE 2: logits =================
    {
        int r0 = gw * 4;   // gw in [0,4096) exactly covers B*S/4 groups
        const float4* e0 = (const float4*)g_WeffT[0];
        const float4* e1 = (const float4*)g_WeffT[1];
        const float4* e2 = (const float4*)g_WeffT[2];
        const float4* hp[4];
        const float4* sp[4];
        #pragma unroll
        for (int r = 0; r < 4; r++) {
            hp[r] = (const float4*)(hidden + (size_t)(r0 + r) * DD);
            sp[r] = (const float4*)(wsub + (size_t)(r0 + r) * DD);
        }
        float acc[4][3];
        #pragma unroll
        for (int r = 0; r < 4; r++) { acc[r][0] = 0.f; acc[r][1] = 0.f; acc[r][2] = 0.f; }

        #pragma unroll
        for (int it = 0; it < 6; it++) {
            int i = it * 32 + lane;
            float4 xx[4];
            #pragma unroll
            for (int r = 0; r < 4; r++) xx[r] = __ldg(hp[r] + i);
            float4 w0 = __ldg(e0 + i), w1 = __ldg(e1 + i), w2 = __ldg(e2 + i);
            #pragma unroll
            for (int r = 0; r < 4; r++) {
                float4 x = xx[r];
                acc[r][0] = fmaf(x.x, w0.x, fmaf(x.y, w0.y, fmaf(x.z, w0.z, fmaf(x.w, w0.w, acc[r][0]))));
                acc[r][1] = fmaf(x.x, w1.x, fmaf(x.y, w1.y, fmaf(x.z, w1.z, fmaf(x.w, w1.w, acc[r][1]))));
                acc[r][2] = fmaf(x.x, w2.x, fmaf(x.y, w2.y, fmaf(x.z, w2.z, fmaf(x.w, w2.w, acc[r][2]))));
            }
        }
        #pragma unroll
        for (int it = 0; it < 6; it++) {
            int i = it * 32 + lane;
            int j = i + DD / 4;
            float4 xx[4];
            #pragma unroll
            for (int r = 0; r < 4; r++) xx[r] = __ldg(sp[r] + i);
            float4 w0 = __ldg(e0 + j), w1 = __ldg(e1 + j), w2 = __ldg(e2 + j);
            #pragma unroll
            for (int r = 0; r < 4; r++) {
                float4 x = xx[r];
                acc[r][0] = fmaf(x.x, w0.x, fmaf(x.y, w0.y, fmaf(x.z, w0.z, fmaf(x.w, w0.w, acc[r][0]))));
                acc[r][1] = fmaf(x.x, w1.x, fmaf(x.y, w1.y, fmaf(x.z, w1.z, fmaf(x.w, w1.w, acc[r][1]))));
                acc[r][2] = fmaf(x.x, w2.x, fmaf(x.y, w2.y, fmaf(x.z, w2.z, fmaf(x.w, w2.w, acc[r][2]))));
            }
        }
        #pragma unroll
        for (int r = 0; r < 4; r++) {
            #pragma unroll
            for (int k = 0; k < 3; k++) {
                float v = acc[r][k];
                #pragma unroll
                for (int o = 16; o; o >>= 1) v += __shfl_xor_sync(0xffffffffu, v, o);
                acc[r][k] = v;
            }
        }
        if (lane == 0) {
            float b0 = g_beff[0], b1 = g_beff[1], b2 = g_beff[2];
            #pragma unroll
            for (int r = 0; r < 4; r++) {
                float* o = g_logits + (size_t)(r0 + r) * KK;
                o[0] = acc[r][0] + b0;
                o[1] = acc[r][1] + b1;
                o[2] = acc[r][2] + b2;
            }
        }
    }

    grid_barrier(1);

    // ================= PHASE 3: CRF (blocks 0..31) =================
    int b = blockIdx.x;
    if (b >= BB) return;

    if (tid == 0) sh_seqlen = 0;
    for (int i = tid; i < SS; i += NT) sh_tgt[i] = tgt[b * SS + i];
    const float* lg = g_logits + (size_t)b * SS * KK;
    for (int i = tid; i < SS * KK; i += NT) sh_log[i] = lg[i];
    __syncthreads();

    {
        int cnt = 0;
        for (int i = tid; i < SS; i += NT) cnt += (sh_tgt[i] >= 1);
        #pragma unroll
        for (int o = 16; o; o >>= 1) cnt += __shfl_xor_sync(0xffffffffu, cnt, o);
        if (lane == 0) atomicAdd(&sh_seqlen, cnt);
    }
    __syncthreads();
    int L = sh_seqlen;

    if (wid == 0) {
        // ---- forward LSE via (lse,+) semiring matrix scan ----
        int idx = L - 1;
        if (idx < 0) idx = 0;
        if (idx > SS - 1) idx = SS - 1;
        float t00 = trans[0], t01 = trans[1], t02 = trans[2];
        float t10 = trans[3], t11 = trans[4], t12 = trans[5];
        float t20 = trans[6], t21 = trans[7], t22 = trans[8];

        float p00 = 0.f,  p01 = SENT, p02 = SENT;
        float p10 = SENT, p11 = 0.f,  p12 = SENT;
        float p20 = SENT, p21 = SENT, p22 = 0.f;

        int tstart = 1 + lane * 16;
        for (int s = 0; s < 16; s++) {
            int t = tstart + s;
            if (t > idx) break;
            float l0 = sh_log[t * 3 + 0], l1 = sh_log[t * 3 + 1], l2 = sh_log[t * 3 + 2];
            float q00 = lse3(p00 + t00, p01 + t10, p02 + t20) + l0;
            float q01 = lse3(p00 + t01, p01 + t11, p02 + t21) + l1;
            float q02 = lse3(p00 + t02, p01 + t12, p02 + t22) + l2;
            float q10 = lse3(p10 + t00, p11 + t10, p12 + t20) + l0;
            float q11 = lse3(p10 + t01, p11 + t11, p12 + t21) + l1;
            float q12 = lse3(p10 + t02, p11 + t12, p12 + t22) + l2;
            float q20 = lse3(p20 + t00, p21 + t10, p22 + t20) + l0;
            float q21 = lse3(p20 + t01, p21 + t11, p22 + t21) + l1;
            float q22 = lse3(p20 + t02, p21 + t12, p22 + t22) + l2;
            p00 = q00; p01 = q01; p02 = q02;
            p10 = q10; p11 = q11; p12 = q12;
            p20 = q20; p21 = q21; p22 = q22;
        }
        for (int d = 1; d < 32; d <<= 1) {
            float q00 = __shfl_down_sync(0xffffffffu, p00, d);
            float q01 = __shfl_down_sync(0xffffffffu, p01, d);
            float q02 = __shfl_down_sync(0xffffffffu, p02, d);
            float q10 = __shfl_down_sync(0xffffffffu, p10, d);
            float q11 = __shfl_down_sync(0xffffffffu, p11, d);
            float q12 = __shfl_down_sync(0xffffffffu, p12, d);
            float q20 = __shfl_down_sync(0xffffffffu, p20, d);
            float q21 = __shfl_down_sync(0xffffffffu, p21, d);
            float q22 = __shfl_down_sync(0xffffffffu, p22, d);
            if ((lane & (2 * d - 1)) == 0) {
                float r00 = lse3(p00 + q00, p01 + q10, p02 + q20);
                float r01 = lse3(p00 + q01, p01 + q11, p02 + q21);
                float r02 = lse3(p00 + q02, p01 + q12, p02 + q22);
                float r10 = lse3(p10 + q00, p11 + q10, p12 + q20);
                float r11 = lse3(p10 + q01, p11 + q11, p12 + q21);
                float r12 = lse3(p10 + q02, p11 + q12, p12 + q22);
                float r20 = lse3(p20 + q00, p21 + q10, p22 + q20);
                float r21 = lse3(p20 + q01, p21 + q11, p22 + q21);
                float r22 = lse3(p20 + q02, p21 + q12, p22 + q22);
                p00 = r00; p01 = r01; p02 = r02;
                p10 = r10; p11 = r11; p12 = r12;
                p20 = r20; p21 = r21; p22 = r22;
            }
        }
        if (lane == 0) {
            float a0 = sh_log[0], a1 = sh_log[1], a2 = sh_log[2];
            float f0 = lse3(a0 + p00, a1 + p10, a2 + p20);
            float f1 = lse3(a0 + p01, a1 + p11, a2 + p21);
            float f2 = lse3(a0 + p02, a1 + p12, a2 + p22);
            float ln = lse3(f0, f1, f2);
            sh_lognorm = (L <= 0) ? 0.0f : ln;
        }
    } else if (wid == 1) {
        // ---- sequential viterbi forward (bit-exact order) with logits prefetch ----
        if (lane == 0) {
            float t00 = trans[0], t01 = trans[1], t02 = trans[2];
            float t10 = trans[3], t11 = trans[4], t12 = trans[5];
            float t20 = trans[6], t21 = trans[7], t22 = trans[8];
            float a0 = sh_log[0], a1 = sh_log[1], a2 = sh_log[2];
            float l0n = sh_log[3], l1n = sh_log[4], l2n = sh_log[5];
            for (int t = 1; t < L; t++) {
                float l0 = l0n, l1 = l1n, l2 = l2n;
                int tn = (t + 1 < SS - 1) ? (t + 1) : (SS - 1);
                l0n = sh_log[tn * 3 + 0]; l1n = sh_log[tn * 3 + 1]; l2n = sh_log[tn * 3 + 2];
                float x0 = a0 + t00, x1 = a1 + t10, x2 = a2 + t20;
                float bst0 = x0; int bi0 = 0;
                if (x1 > bst0) { bst0 = x1; bi0 = 1; }
                if (x2 > bst0) { bst0 = x2; bi0 = 2; }
                float y0 = a0 + t01, y1 = a1 + t11, y2 = a2 + t21;
                float bst1 = y0; int bi1 = 0;
                if (y1 > bst1) { bst1 = y1; bi1 = 1; }
                if (y2 > bst1) { bst1 = y2; bi1 = 2; }
                float z0 = a0 + t02, z1 = a1 + t12, z2 = a2 + t22;
                float bst2 = z0; int bi2 = 0;
                if (z1 > bst2) { bst2 = z1; bi2 = 1; }
                if (z2 > bst2) { bst2 = z2; bi2 = 2; }
                sh_bp[t] = bi0 | (bi1 << 2) | (bi2 << 4);
                a0 = l0 + bst0; a1 = l1 + bst1; a2 = l2 + bst2;
            }
            int tag = 0;
            float bst = a0;
            if (a1 > bst) { bst = a1; tag = 1; }
            if (a2 > bst) { bst = a2; tag = 2; }
            sh_init_tag = (L > 0) ? tag : 0;
        }
        __syncwarp();
        // ---- parallel traceback: suffix scan over packed tag-maps ----
        int init_tag = sh_init_tag;
        bool has_tags = (out_size >= BB * SS);
        int maps[16];
        int acc = IDMAP;
        #pragma unroll
        for (int s = 0; s < 16; s++) {
            int u = lane * 16 + s;
            int t = 510 - u;
            int m = IDMAP;
            if (u <= 510 && t <= L - 2) m = sh_bp[t + 1];
            maps[s] = m;
            acc = mapcompose(m, acc);
        }
        #pragma unroll
        for (int d = 1; d < 32; d <<= 1) {
            int peer = __shfl_up_sync(0xffffffffu, acc, d);
            if (lane >= d) acc = mapcompose(acc, peer);
        }
        int excl = __shfl_up_sync(0xffffffffu, acc, 1);
        if (lane == 0) excl = IDMAP;
        if (has_tags) {
            int g = excl;
            #pragma unroll
            for (int s = 0; s < 16; s++) {
                int u = lane * 16 + s;
                g = mapcompose(maps[s], g);
                if (u <= 510) {
                    int t = 510 - u;
                    int tagt = (t <= L - 1) ? ((g >> (2 * init_tag)) & 3) : 0;
                    out[b * SS + t] = (float)tagt;
                }
            }
            if (lane == 0) {
                int t511 = (L - 1 == SS - 1) ? init_tag : 0;
                out[b * SS + (SS - 1)] = (float)t511;
            }
        }
    } else if (wid == 2) {
        float u = 0.f;
        for (int s = lane; s < SS; s += 32)
            if (s < L) u += sh_log[s * 3 + sh_tgt[s]];
        #pragma unroll
        for (int o = 16; o; o >>= 1) u += __shfl_xor_sync(0xffffffffu, u, o);
        if (lane == 0) sh_unary = u;
    } else if (wid == 3) {
        float v = 0.f;
        for (int s = lane; s < SS - 1; s += 32)
            if (s < L - 1) v += trans[sh_tgt[s] * 3 + sh_tgt[s + 1]];
        #pragma unroll
        for (int o = 16; o; o >>= 1) v += __shfl_xor_sync(0xffffffffu, v, o);
        if (lane == 0) sh_binary = v;
    }
    __syncthreads();

    bool has_tags = (out_size >= BB * SS);
    int ll_off = has_tags ? (BB * SS) : 0;
    if (out_size >= ll_off + BB && tid == 0) {
        out[ll_off + b] = sh_unary + sh_binary - sh_lognorm;
    }
}

// ---------------- launch ----------------
extern "C" void kernel_launch(void* const* d_in, const int* in_sizes, int n_in,
                              void* d_out, int out_size) {
    const float *hidden = nullptr, *wsub = nullptr, *Wc = nullptr, *bc = nullptr;
    const float *Wd = nullptr, *bd = nullptr, *trans = nullptr;
    const int* tgt = nullptr;

    for (int i = 0; i < n_in; i++) {
        int sz = in_sizes[i];
        if (sz == BB * SS * DD) {
            if (!hidden) hidden = (const float*)d_in[i];
            else wsub = (const float*)d_in[i];
        } else if (sz == BB * SS) {
            tgt = (const int*)d_in[i];
        } else if (sz == TWOD * DD) {
            Wc = (const float*)d_in[i];
        } else if (sz == DD) {
            bc = (const float*)d_in[i];
        } else if (sz == DD * KK) {
            Wd = (const float*)d_in[i];
        } else if (sz == KK) {
            bd = (const float*)d_in[i];
        } else if (sz == KK * KK) {
            trans = (const float*)d_in[i];
        }
    }

    fused_kernel<<<NB, NT>>>(hidden, wsub, Wc, Wd, bc, bd, trans, tgt,
                             (float*)d_out, out_size);
}

// round 6
// speedup vs baseline: 1.8087x; 1.0527x over previous
#include <cuda_runtime.h>
#include <math.h>

#define BB 32
#define SS 512
#define DD 768
#define KK 3
#define TWOD 1536

#define NB 512          // blocks (4 per SM guaranteed resident)
#define NT 256          // threads per block (8 warps)

// ---------------- device scratch (no allocs allowed) ----------------
__device__ __align__(16) float g_WeffT[KK][TWOD];
__device__ float g_beff[KK];
__device__ __align__(16) float g_logits[BB * SS * KK];
__device__ unsigned long long g_bar0;       // generation counter (never reset)
__device__ unsigned int g_done[BB];         // per-batch logits arrival counters (never reset)

// ---------------- grid barrier (all blocks resident) ----------------
__device__ __forceinline__ void grid_barrier0() {
    __syncthreads();
    if (threadIdx.x == 0) {
        __threadfence();
        unsigned long long my = atomicAdd(&g_bar0, 1ULL) + 1ULL;
        unsigned long long gen = (my + NB - 1) / NB;
        unsigned long long target = gen * (unsigned long long)NB;
        volatile unsigned long long* p = (volatile unsigned long long*)&g_bar0;
        while (*p < target) { __nanosleep(128); }
        __threadfence();
    }
    __syncthreads();
}

// ---------------- CRF helpers ----------------
#define SENT (-1e38f)

__device__ __forceinline__ float lse3(float x, float y, float z) {
    float m = fmaxf(fmaxf(x, y), z);
    if (m < -1e30f) return SENT;
    return m + __logf(__expf(x - m) + __expf(y - m) + __expf(z - m));
}

__device__ __forceinline__ int mapcompose(int f, int g) {
    int h0 = (f >> (2 * (g & 3))) & 3;
    int h1 = (f >> (2 * ((g >> 2) & 3))) & 3;
    int h2 = (f >> (2 * ((g >> 4) & 3))) & 3;
    return h0 | (h1 << 2) | (h2 << 4);
}
#define IDMAP 0x24

// ---------------- the one kernel ----------------
__global__ void __launch_bounds__(NT, 4)
fused_kernel(const float* __restrict__ hidden, const float* __restrict__ wsub,
             const float* __restrict__ Wc,     const float* __restrict__ Wd,
             const float* __restrict__ bc,     const float* __restrict__ bd,
             const float* __restrict__ trans,  const int* __restrict__ tgt,
             float* __restrict__ out,          int out_size) {
    __shared__ float sh_log[SS * KK];
    __shared__ int sh_tgt[SS];
    __shared__ int sh_bp[SS];
    __shared__ int sh_seqlen;
    __shared__ int sh_init_tag;
    __shared__ unsigned int sh_base;
    __shared__ float sh_lognorm, sh_unary, sh_binary;

    int tid = threadIdx.x;
    int lane = tid & 31;
    int wid = tid >> 5;                       // 0..7
    int gw = blockIdx.x * 8 + wid;            // 0..4095
    int b = blockIdx.x;                       // CRF batch for blocks 0..31

    // baseline of this replay's per-batch counter (read strictly before any
    // increment of this replay: increments happen only after grid_barrier0,
    // which cannot release until every block has executed this line)
    if (b < BB && tid == 0) {
        sh_base = *(volatile unsigned int*)&g_done[b];
        sh_seqlen = 0;
    }

    // ================= PHASE 1: W_eff = W_cnn @ W_dense =================
    if (gw <= TWOD) {
        const float4* s4 = (const float4*)((gw < TWOD) ? (Wc + (size_t)gw * DD) : bc);
        const float4* wd4 = (const float4*)Wd;
        float a0 = 0.f, a1 = 0.f, a2 = 0.f;
        float4 x[6];
        #pragma unroll
        for (int it = 0; it < 6; it++) x[it] = __ldg(s4 + it * 32 + lane);
        #pragma unroll
        for (int it = 0; it < 6; it++) {
            int i = it * 32 + lane;
            float4 wA = __ldg(wd4 + i * 3 + 0);
            float4 wB = __ldg(wd4 + i * 3 + 1);
            float4 wC = __ldg(wd4 + i * 3 + 2);
            float4 v = x[it];
            a0 = fmaf(v.x, wA.x, a0); a1 = fmaf(v.x, wA.y, a1); a2 = fmaf(v.x, wA.z, a2);
            a0 = fmaf(v.y, wA.w, a0); a1 = fmaf(v.y, wB.x, a1); a2 = fmaf(v.y, wB.y, a2);
            a0 = fmaf(v.z, wB.z, a0); a1 = fmaf(v.z, wB.w, a1); a2 = fmaf(v.z, wC.x, a2);
            a0 = fmaf(v.w, wC.y, a0); a1 = fmaf(v.w, wC.z, a1); a2 = fmaf(v.w, wC.w, a2);
        }
        #pragma unroll
        for (int o = 16; o; o >>= 1) {
            a0 += __shfl_xor_sync(0xffffffffu, a0, o);
            a1 += __shfl_xor_sync(0xffffffffu, a1, o);
            a2 += __shfl_xor_sync(0xffffffffu, a2, o);
        }
        if (lane == 0) {
            if (gw < TWOD) {
                g_WeffT[0][gw] = a0;
                g_WeffT[1][gw] = a1;
                g_WeffT[2][gw] = a2;
            } else {
                g_beff[0] = a0 + bd[0];
                g_beff[1] = a1 + bd[1];
                g_beff[2] = a2 + bd[2];
            }
        }
    }

    grid_barrier0();

    // ================= PHASE 2: logits =================
    {
        int r0 = gw * 4;   // gw in [0,4096) exactly covers B*S/4 groups
        const float4* e0 = (const float4*)g_WeffT[0];
        const float4* e1 = (const float4*)g_WeffT[1];
        const float4* e2 = (const float4*)g_WeffT[2];
        const float4* hp[4];
        const float4* sp[4];
        #pragma unroll
        for (int r = 0; r < 4; r++) {
            hp[r] = (const float4*)(hidden + (size_t)(r0 + r) * DD);
            sp[r] = (const float4*)(wsub + (size_t)(r0 + r) * DD);
        }
        float acc[4][3];
        #pragma unroll
        for (int r = 0; r < 4; r++) { acc[r][0] = 0.f; acc[r][1] = 0.f; acc[r][2] = 0.f; }

        #pragma unroll
        for (int it = 0; it < 6; it++) {
            int i = it * 32 + lane;
            float4 xx[4];
            #pragma unroll
            for (int r = 0; r < 4; r++) xx[r] = __ldg(hp[r] + i);
            float4 w0 = __ldg(e0 + i), w1 = __ldg(e1 + i), w2 = __ldg(e2 + i);
            #pragma unroll
            for (int r = 0; r < 4; r++) {
                float4 x = xx[r];
                acc[r][0] = fmaf(x.x, w0.x, fmaf(x.y, w0.y, fmaf(x.z, w0.z, fmaf(x.w, w0.w, acc[r][0]))));
                acc[r][1] = fmaf(x.x, w1.x, fmaf(x.y, w1.y, fmaf(x.z, w1.z, fmaf(x.w, w1.w, acc[r][1]))));
                acc[r][2] = fmaf(x.x, w2.x, fmaf(x.y, w2.y, fmaf(x.z, w2.z, fmaf(x.w, w2.w, acc[r][2]))));
            }
        }
        #pragma unroll
        for (int it = 0; it < 6; it++) {
            int i = it * 32 + lane;
            int j = i + DD / 4;
            float4 xx[4];
            #pragma unroll
            for (int r = 0; r < 4; r++) xx[r] = __ldg(sp[r] + i);
            float4 w0 = __ldg(e0 + j), w1 = __ldg(e1 + j), w2 = __ldg(e2 + j);
            #pragma unroll
            for (int r = 0; r < 4; r++) {
                float4 x = xx[r];
                acc[r][0] = fmaf(x.x, w0.x, fmaf(x.y, w0.y, fmaf(x.z, w0.z, fmaf(x.w, w0.w, acc[r][0]))));
                acc[r][1] = fmaf(x.x, w1.x, fmaf(x.y, w1.y, fmaf(x.z, w1.z, fmaf(x.w, w1.w, acc[r][1]))));
                acc[r][2] = fmaf(x.x, w2.x, fmaf(x.y, w2.y, fmaf(x.z, w2.z, fmaf(x.w, w2.w, acc[r][2]))));
            }
        }
        #pragma unroll
        for (int r = 0; r < 4; r++) {
            #pragma unroll
            for (int k = 0; k < 3; k++) {
                float v = acc[r][k];
                #pragma unroll
                for (int o = 16; o; o >>= 1) v += __shfl_xor_sync(0xffffffffu, v, o);
                acc[r][k] = v;
            }
        }
        if (lane == 0) {
            float b0 = g_beff[0], b1 = g_beff[1], b2 = g_beff[2];
            #pragma unroll
            for (int r = 0; r < 4; r++) {
                float* o = g_logits + (size_t)(r0 + r) * KK;
                o[0] = acc[r][0] + b0;
                o[1] = acc[r][1] + b1;
                o[2] = acc[r][2] + b2;
            }
        }
    }

    // signal: this block's 32 logits rows (batch blockIdx.x/16) are done
    __syncthreads();
    if (tid == 0) {
        __threadfence();
        atomicAdd(&g_done[blockIdx.x >> 4], 1u);
    }

    // ================= PHASE 3: CRF (blocks 0..31) =================
    if (b >= BB) return;

    // prologue that does NOT need logits: targets + seq_len (overlaps the wait)
    for (int i = tid; i < SS; i += NT) sh_tgt[i] = tgt[b * SS + i];
    __syncthreads();
    {
        int cnt = 0;
        for (int i = tid; i < SS; i += NT) cnt += (sh_tgt[i] >= 1);
        #pragma unroll
        for (int o = 16; o; o >>= 1) cnt += __shfl_xor_sync(0xffffffffu, cnt, o);
        if (lane == 0) atomicAdd(&sh_seqlen, cnt);
    }
    __syncthreads();

    // wait for the 16 producer blocks of this batch
    if (tid == 0) {
        unsigned int base = sh_base;
        volatile unsigned int* p = (volatile unsigned int*)&g_done[b];
        while ((unsigned int)(*p - base) < 16u) { __nanosleep(64); }
        __threadfence();
    }
    __syncthreads();

    const float* lg = g_logits + (size_t)b * SS * KK;
    for (int i = tid; i < SS * KK; i += NT) sh_log[i] = lg[i];
    __syncthreads();
    int L = sh_seqlen;

    if (wid == 0) {
        // ---- forward LSE via (lse,+) semiring matrix scan ----
        int idx = L - 1;
        if (idx < 0) idx = 0;
        if (idx > SS - 1) idx = SS - 1;
        float t00 = trans[0], t01 = trans[1], t02 = trans[2];
        float t10 = trans[3], t11 = trans[4], t12 = trans[5];
        float t20 = trans[6], t21 = trans[7], t22 = trans[8];

        float p00 = 0.f,  p01 = SENT, p02 = SENT;
        float p10 = SENT, p11 = 0.f,  p12 = SENT;
        float p20 = SENT, p21 = SENT, p22 = 0.f;

        int tstart = 1 + lane * 16;
        for (int s = 0; s < 16; s++) {
            int t = tstart + s;
            if (t > idx) break;
            float l0 = sh_log[t * 3 + 0], l1 = sh_log[t * 3 + 1], l2 = sh_log[t * 3 + 2];
            float q00 = lse3(p00 + t00, p01 + t10, p02 + t20) + l0;
            float q01 = lse3(p00 + t01, p01 + t11, p02 + t21) + l1;
            float q02 = lse3(p00 + t02, p01 + t12, p02 + t22) + l2;
            float q10 = lse3(p10 + t00, p11 + t10, p12 + t20) + l0;
            float q11 = lse3(p10 + t01, p11 + t11, p12 + t21) + l1;
            float q12 = lse3(p10 + t02, p11 + t12, p12 + t22) + l2;
            float q20 = lse3(p20 + t00, p21 + t10, p22 + t20) + l0;
            float q21 = lse3(p20 + t01, p21 + t11, p22 + t21) + l1;
            float q22 = lse3(p20 + t02, p21 + t12, p22 + t22) + l2;
            p00 = q00; p01 = q01; p02 = q02;
            p10 = q10; p11 = q11; p12 = q12;
            p20 = q20; p21 = q21; p22 = q22;
        }
        for (int d = 1; d < 32; d <<= 1) {
            float q00 = __shfl_down_sync(0xffffffffu, p00, d);
            float q01 = __shfl_down_sync(0xffffffffu, p01, d);
            float q02 = __shfl_down_sync(0xffffffffu, p02, d);
            float q10 = __shfl_down_sync(0xffffffffu, p10, d);
            float q11 = __shfl_down_sync(0xffffffffu, p11, d);
            float q12 = __shfl_down_sync(0xffffffffu, p12, d);
            float q20 = __shfl_down_sync(0xffffffffu, p20, d);
            float q21 = __shfl_down_sync(0xffffffffu, p21, d);
            float q22 = __shfl_down_sync(0xffffffffu, p22, d);
            if ((lane & (2 * d - 1)) == 0) {
                float r00 = lse3(p00 + q00, p01 + q10, p02 + q20);
                float r01 = lse3(p00 + q01, p01 + q11, p02 + q21);
                float r02 = lse3(p00 + q02, p01 + q12, p02 + q22);
                float r10 = lse3(p10 + q00, p11 + q10, p12 + q20);
                float r11 = lse3(p10 + q01, p11 + q11, p12 + q21);
                float r12 = lse3(p10 + q02, p11 + q12, p12 + q22);
                float r20 = lse3(p20 + q00, p21 + q10, p22 + q20);
                float r21 = lse3(p20 + q01, p21 + q11, p22 + q21);
                float r22 = lse3(p20 + q02, p21 + q12, p22 + q22);
                p00 = r00; p01 = r01; p02 = r02;
                p10 = r10; p11 = r11; p12 = r12;
                p20 = r20; p21 = r21; p22 = r22;
            }
        }
        if (lane == 0) {
            float a0 = sh_log[0], a1 = sh_log[1], a2 = sh_log[2];
            float f0 = lse3(a0 + p00, a1 + p10, a2 + p20);
            float f1 = lse3(a0 + p01, a1 + p11, a2 + p21);
            float f2 = lse3(a0 + p02, a1 + p12, a2 + p22);
            float ln = lse3(f0, f1, f2);
            sh_lognorm = (L <= 0) ? 0.0f : ln;
        }
    } else if (wid == 1) {
        // ---- sequential viterbi forward (bit-exact order) with logits prefetch ----
        if (lane == 0) {
            float t00 = trans[0], t01 = trans[1], t02 = trans[2];
            float t10 = trans[3], t11 = trans[4], t12 = trans[5];
            float t20 = trans[6], t21 = trans[7], t22 = trans[8];
            float a0 = sh_log[0], a1 = sh_log[1], a2 = sh_log[2];
            float l0n = sh_log[3], l1n = sh_log[4], l2n = sh_log[5];
            for (int t = 1; t < L; t++) {
                float l0 = l0n, l1 = l1n, l2 = l2n;
                int tn = (t + 1 < SS - 1) ? (t + 1) : (SS - 1);
                l0n = sh_log[tn * 3 + 0]; l1n = sh_log[tn * 3 + 1]; l2n = sh_log[tn * 3 + 2];
                float x0 = a0 + t00, x1 = a1 + t10, x2 = a2 + t20;
                float bst0 = x0; int bi0 = 0;
                if (x1 > bst0) { bst0 = x1; bi0 = 1; }
                if (x2 > bst0) { bst0 = x2; bi0 = 2; }
                float y0 = a0 + t01, y1 = a1 + t11, y2 = a2 + t21;
                float bst1 = y0; int bi1 = 0;
                if (y1 > bst1) { bst1 = y1; bi1 = 1; }
                if (y2 > bst1) { bst1 = y2; bi1 = 2; }
                float z0 = a0 + t02, z1 = a1 + t12, z2 = a2 + t22;
                float bst2 = z0; int bi2 = 0;
                if (z1 > bst2) { bst2 = z1; bi2 = 1; }
                if (z2 > bst2) { bst2 = z2; bi2 = 2; }
                sh_bp[t] = bi0 | (bi1 << 2) | (bi2 << 4);
                a0 = l0 + bst0; a1 = l1 + bst1; a2 = l2 + bst2;
            }
            int tag = 0;
            float bst = a0;
            if (a1 > bst) { bst = a1; tag = 1; }
            if (a2 > bst) { bst = a2; tag = 2; }
            sh_init_tag = (L > 0) ? tag : 0;
        }
        __syncwarp();
        // ---- parallel traceback: suffix scan over packed tag-maps ----
        int init_tag = sh_init_tag;
        bool has_tags = (out_size >= BB * SS);
        int maps[16];
        int acc = IDMAP;
        #pragma unroll
        for (int s = 0; s < 16; s++) {
            int u = lane * 16 + s;
            int t = 510 - u;
            int m = IDMAP;
            if (u <= 510 && t <= L - 2) m = sh_bp[t + 1];
            maps[s] = m;
            acc = mapcompose(m, acc);
        }
        #pragma unroll
        for (int d = 1; d < 32; d <<= 1) {
            int peer = __shfl_up_sync(0xffffffffu, acc, d);
            if (lane >= d) acc = mapcompose(acc, peer);
        }
        int excl = __shfl_up_sync(0xffffffffu, acc, 1);
        if (lane == 0) excl = IDMAP;
        if (has_tags) {
            int g = excl;
            #pragma unroll
            for (int s = 0; s < 16; s++) {
                int u = lane * 16 + s;
                g = mapcompose(maps[s], g);
                if (u <= 510) {
                    int t = 510 - u;
                    int tagt = (t <= L - 1) ? ((g >> (2 * init_tag)) & 3) : 0;
                    out[b * SS + t] = (float)tagt;
                }
            }
            if (lane == 0) {
                int t511 = (L - 1 == SS - 1) ? init_tag : 0;
                out[b * SS + (SS - 1)] = (float)t511;
            }
        }
    } else if (wid == 2) {
        float u = 0.f;
        for (int s = lane; s < SS; s += 32)
            if (s < L) u += sh_log[s * 3 + sh_tgt[s]];
        #pragma unroll
        for (int o = 16; o; o >>= 1) u += __shfl_xor_sync(0xffffffffu, u, o);
        if (lane == 0) sh_unary = u;
    } else if (wid == 3) {
        float v = 0.f;
        for (int s = lane; s < SS - 1; s += 32)
            if (s < L - 1) v += trans[sh_tgt[s] * 3 + sh_tgt[s + 1]];
        #pragma unroll
        for (int o = 16; o; o >>= 1) v += __shfl_xor_sync(0xffffffffu, v, o);
        if (lane == 0) sh_binary = v;
    }
    __syncthreads();

    bool has_tags = (out_size >= BB * SS);
    int ll_off = has_tags ? (BB * SS) : 0;
    if (out_size >= ll_off + BB && tid == 0) {
        out[ll_off + b] = sh_unary + sh_binary - sh_lognorm;
    }
}

// ---------------- launch ----------------
extern "C" void kernel_launch(void* const* d_in, const int* in_sizes, int n_in,
                              void* d_out, int out_size) {
    const float *hidden = nullptr, *wsub = nullptr, *Wc = nullptr, *bc = nullptr;
    const float *Wd = nullptr, *bd = nullptr, *trans = nullptr;
    const int* tgt = nullptr;

    for (int i = 0; i < n_in; i++) {
        int sz = in_sizes[i];
        if (sz == BB * SS * DD) {
            if (!hidden) hidden = (const float*)d_in[i];
            else wsub = (const float*)d_in[i];
        } else if (sz == BB * SS) {
            tgt = (const int*)d_in[i];
        } else if (sz == TWOD * DD) {
            Wc = (const float*)d_in[i];
        } else if (sz == DD) {
            bc = (const float*)d_in[i];
        } else if (sz == DD * KK) {
            Wd = (const float*)d_in[i];
        } else if (sz == KK) {
            bd = (const float*)d_in[i];
        } else if (sz == KK * KK) {
            trans = (const float*)d_in[i];
        }
    }

    fused_kernel<<<NB, NT>>>(hidden, wsub, Wc, Wd, bc, bd, trans, tgt,
                             (float*)d_out, out_size);
}

// round 9
// speedup vs baseline: 1.8211x; 1.0068x over previous
#include <cuda_runtime.h>
#include <math.h>

#define BB 32
#define SS 512
#define DD 768
#define KK 3
#define TWOD 1536

#define NB 512          // blocks (4 per SM guaranteed resident)
#define NT 256          // threads per block (8 warps)

// ---------------- device scratch (no allocs allowed) ----------------
__device__ __align__(16) float g_WeffT[KK][TWOD];
__device__ float g_beff[KK];
__device__ __align__(16) float g_logits[BB * SS * KK];
__device__ unsigned long long g_bar0;       // generation counter (never reset)
__device__ unsigned int g_done[BB];         // per-batch logits arrival counters (never reset)

// ---------------- grid barrier (all blocks resident) ----------------
__device__ __forceinline__ void grid_barrier0() {
    __syncthreads();
    if (threadIdx.x == 0) {
        __threadfence();
        unsigned long long my = atomicAdd(&g_bar0, 1ULL) + 1ULL;
        unsigned long long gen = (my + NB - 1) / NB;
        unsigned long long target = gen * (unsigned long long)NB;
        volatile unsigned long long* p = (volatile unsigned long long*)&g_bar0;
        while (*p < target) { __nanosleep(128); }
        __threadfence();
    }
    __syncthreads();
}

// ---------------- CRF helpers ----------------
#define SENT (-1e38f)

__device__ __forceinline__ float lse3(float x, float y, float z) {
    float m = fmaxf(fmaxf(x, y), z);
    if (m < -1e30f) return SENT;
    return m + __logf(__expf(x - m) + __expf(y - m) + __expf(z - m));
}

__device__ __forceinline__ int mapcompose(int f, int g) {
    int h0 = (f >> (2 * (g & 3))) & 3;
    int h1 = (f >> (2 * ((g >> 2) & 3))) & 3;
    int h2 = (f >> (2 * ((g >> 4) & 3))) & 3;
    return h0 | (h1 << 2) | (h2 << 4);
}
#define IDMAP 0x24

// ---------------- the one kernel ----------------
__global__ void __launch_bounds__(NT, 4)
fused_kernel(const float* __restrict__ hidden, const float* __restrict__ wsub,
             const float* __restrict__ Wc,     const float* __restrict__ Wd,
             const float* __restrict__ bc,     const float* __restrict__ bd,
             const float* __restrict__ trans,  const int* __restrict__ tgt,
             float* __restrict__ out,          int out_size) {
    __shared__ float sh_log[SS * KK];
    __shared__ int sh_tgt[SS];
    __shared__ int sh_bp[SS];
    __shared__ int sh_seqlen;
    __shared__ int sh_init_tag;
    __shared__ unsigned int sh_base;
    __shared__ float sh_lognorm, sh_unary, sh_binary;

    int tid = threadIdx.x;
    int lane = tid & 31;
    int wid = tid >> 5;                       // 0..7
    int gw = blockIdx.x * 8 + wid;            // 0..4095
    int b = blockIdx.x;                       // CRF batch for blocks 0..31

    // per-replay baseline read (strictly before any increment: increments
    // happen only after grid_barrier0, which can't release until every block
    // has executed this)
    if (b < BB && tid == 0) {
        sh_base = *(volatile unsigned int*)&g_done[b];
        sh_seqlen = 0;
    }

    // ================= PHASE 1: W_eff = W_cnn @ W_dense =================
    if (gw <= TWOD) {
        // single base pointer per array; iteration strides are immediates
        // (__ldg is safe here: Wc/bc/Wd are pure kernel inputs)
        const float4* s4 = (const float4*)((gw < TWOD) ? (Wc + (size_t)gw * DD) : bc) + lane;
        const float4* wd4 = (const float4*)Wd + lane * 3;
        float a0 = 0.f, a1 = 0.f, a2 = 0.f;
        float4 x[6];
        #pragma unroll
        for (int it = 0; it < 6; it++) x[it] = __ldg(s4 + it * 32);
        #pragma unroll
        for (int it = 0; it < 6; it++) {
            float4 wA = __ldg(wd4 + it * 96 + 0);
            float4 wB = __ldg(wd4 + it * 96 + 1);
            float4 wC = __ldg(wd4 + it * 96 + 2);
            float4 v = x[it];
            a0 = fmaf(v.x, wA.x, a0); a1 = fmaf(v.x, wA.y, a1); a2 = fmaf(v.x, wA.z, a2);
            a0 = fmaf(v.y, wA.w, a0); a1 = fmaf(v.y, wB.x, a1); a2 = fmaf(v.y, wB.y, a2);
            a0 = fmaf(v.z, wB.z, a0); a1 = fmaf(v.z, wB.w, a1); a2 = fmaf(v.z, wC.x, a2);
            a0 = fmaf(v.w, wC.y, a0); a1 = fmaf(v.w, wC.z, a1); a2 = fmaf(v.w, wC.w, a2);
        }
        #pragma unroll
        for (int o = 16; o; o >>= 1) {
            a0 += __shfl_xor_sync(0xffffffffu, a0, o);
            a1 += __shfl_xor_sync(0xffffffffu, a1, o);
            a2 += __shfl_xor_sync(0xffffffffu, a2, o);
        }
        if (lane == 0) {
            if (gw < TWOD) {
                g_WeffT[0][gw] = a0;
                g_WeffT[1][gw] = a1;
                g_WeffT[2][gw] = a2;
            } else {
                g_beff[0] = a0 + bd[0];
                g_beff[1] = a1 + bd[1];
                g_beff[2] = a2 + bd[2];
            }
        }
    }

    grid_barrier0();

    // ================= PHASE 2: logits =================
    {
        int r0 = gw * 4;   // 4 contiguous rows per warp; gw in [0,4096)
        // one base pointer each; row strides (192 float4) are immediate offsets
        const float4* hb = (const float4*)hidden + (size_t)r0 * 192 + lane;
        const float4* sb = (const float4*)wsub  + (size_t)r0 * 192 + lane;
        // W_eff is written in THIS kernel (phase 1) -> MUST use coherent plain
        // loads, never __ldg (NC path assumes read-only for whole kernel and
        // may be hoisted above the barrier)
        const float4* eb = (const float4*)g_WeffT[0] + lane;   // k stride = 384 float4

        float acc[4][3];
        #pragma unroll
        for (int r = 0; r < 4; r++) { acc[r][0] = 0.f; acc[r][1] = 0.f; acc[r][2] = 0.f; }

        #pragma unroll
        for (int it = 0; it < 6; it++) {
            float4 x0 = __ldg(hb + it * 32 + 0 * 192);
            float4 x1 = __ldg(hb + it * 32 + 1 * 192);
            float4 x2 = __ldg(hb + it * 32 + 2 * 192);
            float4 x3 = __ldg(hb + it * 32 + 3 * 192);
            float4 w0 = eb[it * 32 + 0 * 384];
            float4 w1 = eb[it * 32 + 1 * 384];
            float4 w2 = eb[it * 32 + 2 * 384];
            acc[0][0] = fmaf(x0.x, w0.x, fmaf(x0.y, w0.y, fmaf(x0.z, w0.z, fmaf(x0.w, w0.w, acc[0][0]))));
            acc[0][1] = fmaf(x0.x, w1.x, fmaf(x0.y, w1.y, fmaf(x0.z, w1.z, fmaf(x0.w, w1.w, acc[0][1]))));
            acc[0][2] = fmaf(x0.x, w2.x, fmaf(x0.y, w2.y, fmaf(x0.z, w2.z, fmaf(x0.w, w2.w, acc[0][2]))));
            acc[1][0] = fmaf(x1.x, w0.x, fmaf(x1.y, w0.y, fmaf(x1.z, w0.z, fmaf(x1.w, w0.w, acc[1][0]))));
            acc[1][1] = fmaf(x1.x, w1.x, fmaf(x1.y, w1.y, fmaf(x1.z, w1.z, fmaf(x1.w, w1.w, acc[1][1]))));
            acc[1][2] = fmaf(x1.x, w2.x, fmaf(x1.y, w2.y, fmaf(x1.z, w2.z, fmaf(x1.w, w2.w, acc[1][2]))));
            acc[2][0] = fmaf(x2.x, w0.x, fmaf(x2.y, w0.y, fmaf(x2.z, w0.z, fmaf(x2.w, w0.w, acc[2][0]))));
            acc[2][1] = fmaf(x2.x, w1.x, fmaf(x2.y, w1.y, fmaf(x2.z, w1.z, fmaf(x2.w, w1.w, acc[2][1]))));
            acc[2][2] = fmaf(x2.x, w2.x, fmaf(x2.y, w2.y, fmaf(x2.z, w2.z, fmaf(x2.w, w2.w, acc[2][2]))));
            acc[3][0] = fmaf(x3.x, w0.x, fmaf(x3.y, w0.y, fmaf(x3.z, w0.z, fmaf(x3.w, w0.w, acc[3][0]))));
            acc[3][1] = fmaf(x3.x, w1.x, fmaf(x3.y, w1.y, fmaf(x3.z, w1.z, fmaf(x3.w, w1.w, acc[3][1]))));
            acc[3][2] = fmaf(x3.x, w2.x, fmaf(x3.y, w2.y, fmaf(x3.z, w2.z, fmaf(x3.w, w2.w, acc[3][2]))));
        }
        #pragma unroll
        for (int it = 0; it < 6; it++) {
            float4 x0 = __ldg(sb + it * 32 + 0 * 192);
            float4 x1 = __ldg(sb + it * 32 + 1 * 192);
            float4 x2 = __ldg(sb + it * 32 + 2 * 192);
            float4 x3 = __ldg(sb + it * 32 + 3 * 192);
            // second half of W_eff rows: +192 float4 within each k row
            float4 w0 = eb[it * 32 + 192 + 0 * 384];
            float4 w1 = eb[it * 32 + 192 + 1 * 384];
            float4 w2 = eb[it * 32 + 192 + 2 * 384];
            acc[0][0] = fmaf(x0.x, w0.x, fmaf(x0.y, w0.y, fmaf(x0.z, w0.z, fmaf(x0.w, w0.w, acc[0][0]))));
            acc[0][1] = fmaf(x0.x, w1.x, fmaf(x0.y, w1.y, fmaf(x0.z, w1.z, fmaf(x0.w, w1.w, acc[0][1]))));
            acc[0][2] = fmaf(x0.x, w2.x, fmaf(x0.y, w2.y, fmaf(x0.z, w2.z, fmaf(x0.w, w2.w, acc[0][2]))));
            acc[1][0] = fmaf(x1.x, w0.x, fmaf(x1.y, w0.y, fmaf(x1.z, w0.z, fmaf(x1.w, w0.w, acc[1][0]))));
            acc[1][1] = fmaf(x1.x, w1.x, fmaf(x1.y, w1.y, fmaf(x1.z, w1.z, fmaf(x1.w, w1.w, acc[1][1]))));
            acc[1][2] = fmaf(x1.x, w2.x, fmaf(x1.y, w2.y, fmaf(x1.z, w2.z, fmaf(x1.w, w2.w, acc[1][2]))));
            acc[2][0] = fmaf(x2.x, w0.x, fmaf(x2.y, w0.y, fmaf(x2.z, w0.z, fmaf(x2.w, w0.w, acc[2][0]))));
            acc[2][1] = fmaf(x2.x, w1.x, fmaf(x2.y, w1.y, fmaf(x2.z, w1.z, fmaf(x2.w, w1.w, acc[2][1]))));
            acc[2][2] = fmaf(x2.x, w2.x, fmaf(x2.y, w2.y, fmaf(x2.z, w2.z, fmaf(x2.w, w2.w, acc[2][2]))));
            acc[3][0] = fmaf(x3.x, w0.x, fmaf(x3.y, w0.y, fmaf(x3.z, w0.z, fmaf(x3.w, w0.w, acc[3][0]))));
            acc[3][1] = fmaf(x3.x, w1.x, fmaf(x3.y, w1.y, fmaf(x3.z, w1.z, fmaf(x3.w, w1.w, acc[3][1]))));
            acc[3][2] = fmaf(x3.x, w2.x, fmaf(x3.y, w2.y, fmaf(x3.z, w2.z, fmaf(x3.w, w2.w, acc[3][2]))));
        }
        #pragma unroll
        for (int r = 0; r < 4; r++) {
            #pragma unroll
            for (int k = 0; k < 3; k++) {
                float v = acc[r][k];
                #pragma unroll
                for (int o = 16; o; o >>= 1) v += __shfl_xor_sync(0xffffffffu, v, o);
                acc[r][k] = v;
            }
        }
        if (lane == 0) {
            float b0 = g_beff[0], b1 = g_beff[1], b2 = g_beff[2];
            #pragma unroll
            for (int r = 0; r < 4; r++) {
                float* o = g_logits + (size_t)(r0 + r) * KK;
                o[0] = acc[r][0] + b0;
                o[1] = acc[r][1] + b1;
                o[2] = acc[r][2] + b2;
            }
        }
    }

    // signal: this block's 32 logits rows (batch blockIdx.x/16) are done
    __syncthreads();
    if (tid == 0) {
        __threadfence();
        atomicAdd(&g_done[blockIdx.x >> 4], 1u);
    }

    // ================= PHASE 3: CRF (blocks 0..31) =================
    if (b >= BB) return;

    // prologue that does NOT need logits: targets + seq_len (overlaps the wait)
    for (int i = tid; i < SS; i += NT) sh_tgt[i] = tgt[b * SS + i];
    __syncthreads();
    {
        int cnt = 0;
        for (int i = tid; i < SS; i += NT) cnt += (sh_tgt[i] >= 1);
        #pragma unroll
        for (int o = 16; o; o >>= 1) cnt += __shfl_xor_sync(0xffffffffu, cnt, o);
        if (lane == 0) atomicAdd(&sh_seqlen, cnt);
    }
    __syncthreads();

    // wait for the 16 producer blocks of this batch
    if (tid == 0) {
        unsigned int base = sh_base;
        volatile unsigned int* p = (volatile unsigned int*)&g_done[b];
        while ((unsigned int)(*p - base) < 16u) { __nanosleep(64); }
        __threadfence();
    }
    __syncthreads();

    const float* lg = g_logits + (size_t)b * SS * KK;
    for (int i = tid; i < SS * KK; i += NT) sh_log[i] = lg[i];
    __syncthreads();
    int L = sh_seqlen;

    if (wid == 0) {
        // ---- forward LSE via (lse,+) semiring matrix scan ----
        int idx = L - 1;
        if (idx < 0) idx = 0;
        if (idx > SS - 1) idx = SS - 1;
        float t00 = trans[0], t01 = trans[1], t02 = trans[2];
        float t10 = trans[3], t11 = trans[4], t12 = trans[5];
        float t20 = trans[6], t21 = trans[7], t22 = trans[8];

        float p00 = 0.f,  p01 = SENT, p02 = SENT;
        float p10 = SENT, p11 = 0.f,  p12 = SENT;
        float p20 = SENT, p21 = SENT, p22 = 0.f;

        int tstart = 1 + lane * 16;
        for (int s = 0; s < 16; s++) {
            int t = tstart + s;
            if (t > idx) break;
            float l0 = sh_log[t * 3 + 0], l1 = sh_log[t * 3 + 1], l2 = sh_log[t * 3 + 2];
            float q00 = lse3(p00 + t00, p01 + t10, p02 + t20) + l0;
            float q01 = lse3(p00 + t01, p01 + t11, p02 + t21) + l1;
            float q02 = lse3(p00 + t02, p01 + t12, p02 + t22) + l2;
            float q10 = lse3(p10 + t00, p11 + t10, p12 + t20) + l0;
            float q11 = lse3(p10 + t01, p11 + t11, p12 + t21) + l1;
            float q12 = lse3(p10 + t02, p11 + t12, p12 + t22) + l2;
            float q20 = lse3(p20 + t00, p21 + t10, p22 + t20) + l0;
            float q21 = lse3(p20 + t01, p21 + t11, p22 + t21) + l1;
            float q22 = lse3(p20 + t02, p21 + t12, p22 + t22) + l2;
            p00 = q00; p01 = q01; p02 = q02;
            p10 = q10; p11 = q11; p12 = q12;
            p20 = q20; p21 = q21; p22 = q22;
        }
        for (int d = 1; d < 32; d <<= 1) {
            float q00 = __shfl_down_sync(0xffffffffu, p00, d);
            float q01 = __shfl_down_sync(0xffffffffu, p01, d);
            float q02 = __shfl_down_sync(0xffffffffu, p02, d);
            float q10 = __shfl_down_sync(0xffffffffu, p10, d);
            float q11 = __shfl_down_sync(0xffffffffu, p11, d);
            float q12 = __shfl_down_sync(0xffffffffu, p12, d);
            float q20 = __shfl_down_sync(0xffffffffu, p20, d);
            float q21 = __shfl_down_sync(0xffffffffu, p21, d);
            float q22 = __shfl_down_sync(0xffffffffu, p22, d);
            if ((lane & (2 * d - 1)) == 0) {
                float r00 = lse3(p00 + q00, p01 + q10, p02 + q20);
                float r01 = lse3(p00 + q01, p01 + q11, p02 + q21);
                float r02 = lse3(p00 + q02, p01 + q12, p02 + q22);
                float r10 = lse3(p10 + q00, p11 + q10, p12 + q20);
                float r11 = lse3(p10 + q01, p11 + q11, p12 + q21);
                float r12 = lse3(p10 + q02, p11 + q12, p12 + q22);
                float r20 = lse3(p20 + q00, p21 + q10, p22 + q20);
                float r21 = lse3(p20 + q01, p21 + q11, p22 + q21);
                float r22 = lse3(p20 + q02, p21 + q12, p22 + q22);
                p00 = r00; p01 = r01; p02 = r02;
                p10 = r10; p11 = r11; p12 = r12;
                p20 = r20; p21 = r21; p22 = r22;
            }
        }
        if (lane == 0) {
            float a0 = sh_log[0], a1 = sh_log[1], a2 = sh_log[2];
            float f0 = lse3(a0 + p00, a1 + p10, a2 + p20);
            float f1 = lse3(a0 + p01, a1 + p11, a2 + p21);
            float f2 = lse3(a0 + p02, a1 + p12, a2 + p22);
            float ln = lse3(f0, f1, f2);
            sh_lognorm = (L <= 0) ? 0.0f : ln;
        }
    } else if (wid == 1) {
        // ---- sequential viterbi forward (bit-exact order) with logits prefetch ----
        if (lane == 0) {
            float t00 = trans[0], t01 = trans[1], t02 = trans[2];
            float t10 = trans[3], t11 = trans[4], t12 = trans[5];
            float t20 = trans[6], t21 = trans[7], t22 = trans[8];
            float a0 = sh_log[0], a1 = sh_log[1], a2 = sh_log[2];
            float l0n = sh_log[3], l1n = sh_log[4], l2n = sh_log[5];
            for (int t = 1; t < L; t++) {
                float l0 = l0n, l1 = l1n, l2 = l2n;
                int tn = (t + 1 < SS - 1) ? (t + 1) : (SS - 1);
                l0n = sh_log[tn * 3 + 0]; l1n = sh_log[tn * 3 + 1]; l2n = sh_log[tn * 3 + 2];
                float x0 = a0 + t00, x1 = a1 + t10, x2 = a2 + t20;
                float bst0 = x0; int bi0 = 0;
                if (x1 > bst0) { bst0 = x1; bi0 = 1; }
                if (x2 > bst0) { bst0 = x2; bi0 = 2; }
                float y0 = a0 + t01, y1 = a1 + t11, y2 = a2 + t21;
                float bst1 = y0; int bi1 = 0;
                if (y1 > bst1) { bst1 = y1; bi1 = 1; }
                if (y2 > bst1) { bst1 = y2; bi1 = 2; }
                float z0 = a0 + t02, z1 = a1 + t12, z2 = a2 + t22;
                float bst2 = z0; int bi2 = 0;
                if (z1 > bst2) { bst2 = z1; bi2 = 1; }
                if (z2 > bst2) { bst2 = z2; bi2 = 2; }
                sh_bp[t] = bi0 | (bi1 << 2) | (bi2 << 4);
                a0 = l0 + bst0; a1 = l1 + bst1; a2 = l2 + bst2;
            }
            int tag = 0;
            float bst = a0;
            if (a1 > bst) { bst = a1; tag = 1; }
            if (a2 > bst) { bst = a2; tag = 2; }
            sh_init_tag = (L > 0) ? tag : 0;
        }
        __syncwarp();
        // ---- parallel traceback: suffix scan over packed tag-maps ----
        int init_tag = sh_init_tag;
        bool has_tags = (out_size >= BB * SS);
        int maps[16];
        int acc = IDMAP;
        #pragma unroll
        for (int s = 0; s < 16; s++) {
            int u = lane * 16 + s;
            int t = 510 - u;
            int m = IDMAP;
            if (u <= 510 && t <= L - 2) m = sh_bp[t + 1];
            maps[s] = m;
            acc = mapcompose(m, acc);
        }
        #pragma unroll
        for (int d = 1; d < 32; d <<= 1) {
            int peer = __shfl_up_sync(0xffffffffu, acc, d);
            if (lane >= d) acc = mapcompose(acc, peer);
        }
        int excl = __shfl_up_sync(0xffffffffu, acc, 1);
        if (lane == 0) excl = IDMAP;
        if (has_tags) {
            int g = excl;
            #pragma unroll
            for (int s = 0; s < 16; s++) {
                int u = lane * 16 + s;
                g = mapcompose(maps[s], g);
                if (u <= 510) {
                    int t = 510 - u;
                    int tagt = (t <= L - 1) ? ((g >> (2 * init_tag)) & 3) : 0;
                    out[b * SS + t] = (float)tagt;
                }
            }
            if (lane == 0) {
                int t511 = (L - 1 == SS - 1) ? init_tag : 0;
                out[b * SS + (SS - 1)] = (float)t511;
            }
        }
    } else if (wid == 2) {
        float u = 0.f;
        for (int s = lane; s < SS; s += 32)
            if (s < L) u += sh_log[s * 3 + sh_tgt[s]];
        #pragma unroll
        for (int o = 16; o; o >>= 1) u += __shfl_xor_sync(0xffffffffu, u, o);
        if (lane == 0) sh_unary = u;
    } else {
        float v = 0.f;
        for (int s = lane; s < SS - 1; s += 32)
            if (s < L - 1) v += trans[sh_tgt[s] * 3 + sh_tgt[s + 1]];
        #pragma unroll
        for (int o = 16; o; o >>= 1) v += __shfl_xor_sync(0xffffffffu, v, o);
        if (lane == 0) sh_binary = v;
    }
    __syncthreads();

    bool has_tags = (out_size >= BB * SS);
    int ll_off = has_tags ? (BB * SS) : 0;
    if (out_size >= ll_off + BB && tid == 0) {
        out[ll_off + b] = sh_unary + sh_binary - sh_lognorm;
    }
}

// ---------------- launch ----------------
extern "C" void kernel_launch(void* const* d_in, const int* in_sizes, int n_in,
                              void* d_out, int out_size) {
    const float *hidden = nullptr, *wsub = nullptr, *Wc = nullptr, *bc = nullptr;
    const float *Wd = nullptr, *bd = nullptr, *trans = nullptr;
    const int* tgt = nullptr;

    for (int i = 0; i < n_in; i++) {
        int sz = in_sizes[i];
        if (sz == BB * SS * DD) {
            if (!hidden) hidden = (const float*)d_in[i];
            else wsub = (const float*)d_in[i];
        } else if (sz == BB * SS) {
            tgt = (const int*)d_in[i];
        } else if (sz == TWOD * DD) {
            Wc = (const float*)d_in[i];
        } else if (sz == DD) {
            bc = (const float*)d_in[i];
        } else if (sz == DD * KK) {
            Wd = (const float*)d_in[i];
        } else if (sz == KK) {
            bd = (const float*)d_in[i];
        } else if (sz == KK * KK) {
            trans = (const float*)d_in[i];
        }
    }

    fused_kernel<<<NB, NT>>>(hidden, wsub, Wc, Wd, bc, bd, trans, tgt,
                             (float*)d_out, out_size);
}